// round 15
// baseline (speedup 1.0000x reference)
#include <cuda_runtime.h>

#define NB 256
#define NH 3
#define CC 64
#define NN 23
#define LL 35
#define FEAT 529
#define KINV (1.0f/2240.0f)

typedef unsigned long long ull;

__device__ __forceinline__ void fma2(ull& d, ull a, ull b) {
    asm("fma.rn.f32x2 %0, %1, %2, %0;" : "+l"(d) : "l"(a), "l"(b));
}
__device__ __forceinline__ void add2(ull& d, ull a) {
    asm("add.rn.f32x2 %0, %0, %1;" : "+l"(d) : "l"(a));
}
__device__ __forceinline__ ull dup2(float v) {
    ull r; unsigned u = __float_as_uint(v);
    asm("mov.b64 %0, {%1, %1};" : "=l"(r) : "r"(u));
    return r;
}
__device__ __forceinline__ void unpk(ull v, float& lo, float& hi) {
    unsigned a, b;
    asm("mov.b64 {%0, %1}, %2;" : "=r"(a), "=r"(b) : "l"(v));
    lo = __uint_as_float(a); hi = __uint_as_float(b);
}

// ---------------- device scratch ----------------
__device__ float g_GT[64*192];       // [c1*192 + h*64+c2]
__device__ float g_mwT[64*192];      // [c*192 + h*64+o]
__device__ float g_v1[NH*CC];
__device__ float g_v2[NH*CC];
__device__ float g_sc[NH];
__device__ float g_attm[NB*NH*FEAT];   // half 0 partial (then sum after k2)
__device__ float g_attmB[NB*NH*FEAT];  // half 1 partial
__device__ float g_scale[NH*FEAT];
__device__ float g_shift[NH*FEAT];
__device__ float g_A[NB*NH*FEAT];
__device__ float g_gcn[NB*CC*NN*LL];

// ---------------- k0: G^T, v1, v2, s ----------------
__global__ void k0_pre(const float* __restrict__ cw1, const float* __restrict__ cb1,
                       const float* __restrict__ cw2, const float* __restrict__ cb2) {
    __shared__ float s1[4096];
    __shared__ float s2[4096];
    int h = blockIdx.x, t = threadIdx.x;
    for (int i = t; i < 4096; i += 256) { s1[i] = cw1[h*4096+i]; s2[i] = cw2[h*4096+i]; }
    __syncthreads();
    for (int e = t; e < 4096; e += 256) {
        int c2 = e >> 6, c1 = e & 63;
        float acc = 0.f;
        #pragma unroll 8
        for (int o = 0; o < 64; o++) acc += s2[o*64+c2] * s1[o*64+c1];
        g_GT[c1*192 + h*64 + c2] = acc;
    }
    if (t < 64) {
        float a1 = 0.f, a2 = 0.f;
        for (int o = 0; o < 64; o++) {
            a1 += cb2[h*64+o] * s1[o*64+t];
            a2 += cb1[h*64+o] * s2[o*64+t];
        }
        g_v1[h*64+t] = a1;
        g_v2[h*64+t] = a2;
    }
    if (t == 64) {
        float a = 0.f;
        for (int o = 0; o < 64; o++) a += cb1[h*64+o]*cb2[h*64+o];
        g_sc[h] = a;
    }
}

// ---------------- k0b: mw^T ----------------
__global__ void k0b_mwt(const float* __restrict__ mw) {
    int i = blockIdx.x * 256 + threadIdx.x;
    if (i < 12288) {
        int c = i / 192, row = i % 192;
        g_mwT[i] = mw[row*64 + c];
    }
}

// ---------------- k1: attention, per-(head, l-half) blocks, occ 4 ----------
// smem floats: sG 4096 | sxt 3072 | sW2 3200 | sXs 1472 | st1 24 | st2 24
// total 11888 floats = 47,552 B -> 4 blocks/SM (190 KB)
#define SM1_FLOATS (4096 + 3072 + 3200 + 1472 + 24 + 24)

__global__ __launch_bounds__(256, 4) void k1_attm(const float* __restrict__ x) {
    extern __shared__ float sm[];
    float* sG  = sm;            // [c1*64 + row]  (one head)
    float* sxt = sm + 4096;     // [c*48 + n*2 + li], n padded to 24
    float* sW2 = sm + 7168;     // [(row*25 + n)*2 + li], 25-pair row stride
    float* sXs = sm + 10368;    // [c*23 + n]
    float* st1 = sm + 11840;    // 24
    float* st2 = sm + 11864;    // 24

    int blk = blockIdx.x;            // b*6 + h*2 + half
    int b = blk / 6;
    int rem = blk - b*6;
    int h = rem >> 1, half = rem & 1;
    int t = threadIdx.x;

    for (int i = t; i < 4096; i += 256)
        sG[i] = g_GT[(i >> 6)*192 + h*64 + (i & 63)];
    for (int i = t; i < 1472; i += 256) sXs[i] = 0.f;

    // W mapping (t < 128): rows {wr, wr+32}, col-tile of 6 pairs at wn0
    int wr = t & 31, wct = t >> 5;   // wct == warp id; valid 0..3
    int wn0 = wct * 6;
    bool wact = (t < 128);

    // Q mapping: s = tile (8x8 of 3m x 3n), qg = c2 group (16 c2 each)
    int s = t & 63, qg = t >> 6;
    int m0 = (s & 7) * 3, nq0 = (s >> 3) * 3;
    int c2lo = qg * 16;

    ull qp[9];
    #pragma unroll
    for (int k = 0; k < 9; k++) qp[k] = 0ULL;

    const float* xb = x + b * (64*23*35);
    int p0 = half ? 9 : 0;
    int p1 = half ? 18 : 9;

    for (int p = p0; p < p1; p++) {
        __syncthreads();   // prev Q done reading sxt/sW2 (and fills on first)
        int l0 = 2*p;
        for (int idx = t; idx < 3072; idx += 256) {
            int c = idx / 48, r = idx - c*48;
            int n = r >> 1, li = r & 1;
            int l = l0 + li;
            sxt[idx] = (n < 23 && l < 35) ? xb[(c*23 + n)*35 + l] : 0.f;
        }
        __syncthreads();

        // Xs accumulation (owner-computes)
        for (int e = t; e < 1472; e += 256) {
            int c = e / 23, n = e - c*23;
            sXs[e] += sxt[c*48 + n*2] + sxt[c*48 + n*2 + 1];
        }

        // ---- W phase (warps 0-3): W2[row][n] = sum_c1 G[row,c1]*x2[c1,n]
        if (wact) {
            ull w2a[6], w2b[6];
            #pragma unroll
            for (int j = 0; j < 6; j++) { w2a[j] = 0ULL; w2b[j] = 0ULL; }
            #pragma unroll 4
            for (int c1 = 0; c1 < 64; c1++) {
                ull da = dup2(sG[c1*64 + wr]);
                ull db = dup2(sG[c1*64 + wr + 32]);
                #pragma unroll
                for (int j = 0; j < 6; j++) {
                    ull xv = *reinterpret_cast<const ull*>(&sxt[c1*48 + (wn0+j)*2]);
                    fma2(w2a[j], da, xv);
                    fma2(w2b[j], db, xv);
                }
            }
            #pragma unroll
            for (int j = 0; j < 6; j++) {
                *reinterpret_cast<ull*>(&sW2[(wr*25 + wn0+j)*2])      = w2a[j];
                *reinterpret_cast<ull*>(&sW2[((wr+32)*25 + wn0+j)*2]) = w2b[j];
            }
        }
        __syncthreads();   // sW2 visible

        // ---- Q phase (all threads): qp += sum over this group's 16 c2
        #pragma unroll 2
        for (int cc = 0; cc < 16; cc++) {
            int c2 = c2lo + cc;
            ull xm[3], wn[3];
            #pragma unroll
            for (int i = 0; i < 3; i++)
                xm[i] = *reinterpret_cast<const ull*>(&sxt[c2*48 + (m0+i)*2]);
            #pragma unroll
            for (int j = 0; j < 3; j++)
                wn[j] = *reinterpret_cast<const ull*>(&sW2[(c2*25 + nq0+j)*2]);
            #pragma unroll
            for (int i = 0; i < 3; i++)
                #pragma unroll
                for (int j = 0; j < 3; j++)
                    fma2(qp[i*3+j], xm[i], wn[j]);
        }
    }
    __syncthreads();   // loop done; sG/sxt/sW2 now dead

    // stash partials from groups 1..3 into dead sG region
    ull* sRed = reinterpret_cast<ull*>(sG);
    if (qg > 0) {
        #pragma unroll
        for (int k = 0; k < 9; k++)
            sRed[((qg-1)*64 + s)*9 + k] = qp[k];
    }
    // bias vectors (group-0 threads only; no overlap with sRed writers)
    if (t < 23) {
        float a = 0.f;
        #pragma unroll 8
        for (int c = 0; c < 64; c++) a += g_v1[h*64 + c] * sXs[c*23 + t];
        st1[t] = a;
    } else if (t >= 32 && t < 55) {
        int m = t - 32;
        float a = 0.f;
        #pragma unroll 8
        for (int c = 0; c < 64; c++) a += g_v2[h*64 + c] * sXs[c*23 + m];
        st2[m] = a;
    }
    __syncthreads();

    if (qg == 0) {
        #pragma unroll
        for (int gg = 0; gg < 3; gg++)
            #pragma unroll
            for (int k = 0; k < 9; k++)
                add2(qp[k], sRed[(gg*64 + s)*9 + k]);
        float base = (half ? 17.0f : 18.0f) * g_sc[h];
        float* dst = (half ? g_attmB : g_attm) + (b*NH + h)*FEAT;
        #pragma unroll
        for (int i = 0; i < 3; i++) {
            int m = m0 + i; if (m >= 23) continue;
            #pragma unroll
            for (int j = 0; j < 3; j++) {
                int n = nq0 + j; if (n >= 23) continue;
                float lo, hi; unpk(qp[i*3+j], lo, hi);
                dst[m*23 + n] = (lo + hi + st2[m] + st1[n] + base) * KINV;
            }
        }
    }
}

// ---------------- k2: sum halves + BN stats (writes summed attm back) ------
__global__ void k2_bn(const float* __restrict__ gamma, const float* __restrict__ beta) {
    __shared__ float ss[256];
    __shared__ float sq[256];
    int f = blockIdx.x, t = threadIdx.x;
    int idx = t*(NH*FEAT) + f;
    float v = g_attm[idx] + g_attmB[idx];
    g_attm[idx] = v;                      // write back so k3 reads the sum
    ss[t] = v; sq[t] = v*v;
    __syncthreads();
    for (int s = 128; s > 0; s >>= 1) {
        if (t < s) { ss[t] += ss[t+s]; sq[t] += sq[t+s]; }
        __syncthreads();
    }
    if (t == 0) {
        float mean = ss[0] * (1.0f/256.0f);
        float var  = sq[0] * (1.0f/256.0f) - mean*mean;
        float sc = gamma[f] * rsqrtf(var + 1e-5f);
        g_scale[f] = sc;
        g_shift[f] = beta[f] - mean * sc;
    }
}

// ---------------- k3: BN apply + softmax(-2) + A ----------------
__global__ void k3_soft(const float* __restrict__ att, const float* __restrict__ A_ske) {
    __shared__ float sy[FEAT];
    int bh = blockIdx.x, h = bh % 3, t = threadIdx.x;
    for (int e = t; e < FEAT; e += 256)
        sy[e] = g_attm[bh*FEAT + e] * g_scale[h*FEAT + e] + g_shift[h*FEAT + e];
    __syncthreads();
    if (t < 23) {
        float mx = -1e30f;
        for (int m = 0; m < 23; m++) mx = fmaxf(mx, sy[m*23 + t]);
        float ssum = 0.f;
        for (int m = 0; m < 23; m++) {
            float e = expf(sy[m*23 + t] - mx);
            sy[m*23 + t] = e; ssum += e;
        }
        float inv = 1.0f / ssum;
        for (int m = 0; m < 23; m++) sy[m*23 + t] *= inv;
    }
    __syncthreads();
    for (int e = t; e < FEAT; e += 256)
        g_A[bh*FEAT + e] = A_ske[h*FEAT + e] + att[h*FEAT + e] + sy[e];
}

// ---------------- k4: graph convolution, f32x2, l-chunks of 6 (R9 exact) ----
// smem floats: sA 1588 | sxt 9216 | sMX 9344 | smwT 4096
#define SM4_FLOATS (1588 + 9216 + 9344 + 4096)

__global__ __launch_bounds__(256, 2) void k4_gcn(const float* __restrict__ x,
                                                 const float* __restrict__ mb) {
    extern __shared__ float sm[];
    float* sA   = sm;             // [h*529 + n*23 + m], padded to 1588
    float* sxt  = sA + 1588;      // [c*144 + n*6 + li], zero-pad  (8B-aligned)
    float* sMX  = sxt + 9216;     // [o*146 + n*6 + li]            (8B-aligned)
    float* smwT = sMX + 9344;     // [c*64 + o]

    int blk = blockIdx.x;
    int b = blk / 6, ch = blk % 6;
    int l0 = ch * 6;
    int t = threadIdx.x;

    for (int i = t; i < 1587; i += 256) sA[i] = g_A[b*1587 + i];
    for (int idx = t; idx < 9216; idx += 256) {
        int c = idx / 144, r = idx - c*144;
        int n = r / 6, li = r - n*6;
        int l = l0 + li;
        sxt[idx] = (n < 23 && l < 35) ? x[((b*64 + c)*23 + n)*35 + l] : 0.f;
    }

    int ro = t & 31, pg0 = (t >> 5) * 9;
    int go = t & 63, m0 = (t >> 6) * 6;
    ull gacc[6][3];
    #pragma unroll
    for (int j = 0; j < 6; j++)
        #pragma unroll
        for (int lp = 0; lp < 3; lp++) gacc[j][lp] = 0ULL;

    for (int h = 0; h < NH; h++) {
        __syncthreads();
        for (int i = t; i < 4096; i += 256)
            smwT[i] = g_mwT[(i >> 6)*192 + h*64 + (i & 63)];
        __syncthreads();

        {
            ull a0[9], a1[9];
            #pragma unroll
            for (int q = 0; q < 9; q++) { a0[q] = 0ULL; a1[q] = 0ULL; }
            #pragma unroll 4
            for (int c = 0; c < 64; c++) {
                ull w0 = dup2(smwT[c*64 + ro]);
                ull w1 = dup2(smwT[c*64 + ro + 32]);
                #pragma unroll
                for (int q = 0; q < 9; q++) {
                    ull xv = *reinterpret_cast<const ull*>(&sxt[c*144 + 2*(pg0+q)]);
                    fma2(a0[q], w0, xv);
                    fma2(a1[q], w1, xv);
                }
            }
            #pragma unroll
            for (int q = 0; q < 9; q++) {
                *reinterpret_cast<ull*>(&sMX[ro*146 + 2*(pg0+q)]) = a0[q];
                *reinterpret_cast<ull*>(&sMX[(ro+32)*146 + 2*(pg0+q)]) = a1[q];
            }
        }
        __syncthreads();

        #pragma unroll 1
        for (int n = 0; n < 23; n++) {
            ull mx2[3];
            #pragma unroll
            for (int lp = 0; lp < 3; lp++)
                mx2[lp] = *reinterpret_cast<const ull*>(&sMX[go*146 + n*6 + 2*lp]);
            #pragma unroll
            for (int j = 0; j < 6; j++) {
                int m = m0 + j; if (m > 22) m = 22;
                ull av = dup2(sA[h*FEAT + n*23 + m]);
                #pragma unroll
                for (int lp = 0; lp < 3; lp++)
                    fma2(gacc[j][lp], av, mx2[lp]);
            }
        }
    }

    float mbs = mb[go] + mb[64 + go] + mb[128 + go];
    #pragma unroll
    for (int j = 0; j < 6; j++) {
        int m = m0 + j; if (m >= 23) continue;
        #pragma unroll
        for (int lp = 0; lp < 3; lp++) {
            float lo, hi; unpk(gacc[j][lp], lo, hi);
            int l = l0 + 2*lp;
            float* dst = &g_gcn[((b*64 + go)*23 + m)*35 + l];
            if (l < 35)     dst[0] = lo + mbs;
            if (l + 1 < 35) dst[1] = hi + mbs;
        }
    }
}

// ---------------- k5: out = gcn @ ws + bias, f32x2 (R9 exact) ----------------
__global__ __launch_bounds__(288) void k5_out(const float* __restrict__ ws,
                                              const float* __restrict__ bias,
                                              float* __restrict__ out) {
    __shared__ float sws2[35*36];
    __shared__ float sb[36];
    __shared__ float srow[64*35];
    int t = threadIdx.x;
    for (int i = t; i < 35*36; i += 288) {
        int l = i / 36, j = i - l*36;
        sws2[i] = (j < 35) ? ws[l*35 + j] : 0.f;
    }
    if (t < 36) sb[t] = (t < 35) ? bias[t] : 0.f;
    long long base = (long long)blockIdx.x * 2240;
    for (int i = t; i < 2240; i += 288) srow[i] = g_gcn[base + i];
    __syncthreads();

    int rg = t / 9, jg = t - rg*9;
    int r0 = rg*2;
    ull a00 = 0ULL, a01 = 0ULL, a10 = 0ULL, a11 = 0ULL;
    #pragma unroll 5
    for (int l = 0; l < 35; l++) {
        ull w0 = *reinterpret_cast<const ull*>(&sws2[l*36 + 4*jg]);
        ull w1 = *reinterpret_cast<const ull*>(&sws2[l*36 + 4*jg + 2]);
        ull s0 = dup2(srow[r0*35 + l]);
        ull s1 = dup2(srow[r0*35 + 35 + l]);
        fma2(a00, s0, w0); fma2(a01, s0, w1);
        fma2(a10, s1, w0); fma2(a11, s1, w1);
    }

    float v[2][4];
    unpk(a00, v[0][0], v[0][1]); unpk(a01, v[0][2], v[0][3]);
    unpk(a10, v[1][0], v[1][1]); unpk(a11, v[1][2], v[1][3]);
    #pragma unroll
    for (int rr = 0; rr < 2; rr++) {
        long long ob = base + (long long)(r0 + rr) * 35;
        #pragma unroll
        for (int q = 0; q < 4; q++) {
            int j = 4*jg + q;
            if (j < 35) out[ob + j] = v[rr][q] + sb[j];
        }
    }
}

// ---------------- host launch ----------------
extern "C" void kernel_launch(void* const* d_in, const int* in_sizes, int n_in,
                              void* d_out, int out_size) {
    const float* x      = (const float*)d_in[0];
    const float* cw1    = (const float*)d_in[1];
    const float* cb1    = (const float*)d_in[2];
    const float* cw2    = (const float*)d_in[3];
    const float* cb2    = (const float*)d_in[4];
    const float* gamma  = (const float*)d_in[5];
    const float* beta   = (const float*)d_in[6];
    const float* mw     = (const float*)d_in[7];
    const float* mb     = (const float*)d_in[8];
    const float* att    = (const float*)d_in[9];
    const float* A_ske  = (const float*)d_in[10];
    const float* ws     = (const float*)d_in[11];
    const float* bias   = (const float*)d_in[12];
    float* out = (float*)d_out;

    cudaFuncSetAttribute(k1_attm, cudaFuncAttributeMaxDynamicSharedMemorySize,
                         SM1_FLOATS * (int)sizeof(float));
    cudaFuncSetAttribute(k4_gcn, cudaFuncAttributeMaxDynamicSharedMemorySize,
                         SM4_FLOATS * (int)sizeof(float));

    k0_pre<<<NH, 256>>>(cw1, cb1, cw2, cb2);
    k0b_mwt<<<48, 256>>>(mw);
    k1_attm<<<NB*6, 256, SM1_FLOATS * sizeof(float)>>>(x);   // (b, head, l-half)
    k2_bn<<<NH*FEAT, 256>>>(gamma, beta);
    k3_soft<<<NB*NH, 256>>>(att, A_ske);
    k4_gcn<<<NB*6, 256, SM4_FLOATS * sizeof(float)>>>(x, mb);
    k5_out<<<5888, 288>>>(ws, bias, out);
}

// round 16
// speedup vs baseline: 1.0483x; 1.0483x over previous
#include <cuda_runtime.h>

#define NB 256
#define NH 3
#define CC 64
#define NN 23
#define LL 35
#define FEAT 529
#define KINV (1.0f/2240.0f)

typedef unsigned long long ull;

__device__ __forceinline__ void fma2(ull& d, ull a, ull b) {
    asm("fma.rn.f32x2 %0, %1, %2, %0;" : "+l"(d) : "l"(a), "l"(b));
}
__device__ __forceinline__ ull dup2(float v) {
    ull r; unsigned u = __float_as_uint(v);
    asm("mov.b64 %0, {%1, %1};" : "=l"(r) : "r"(u));
    return r;
}
__device__ __forceinline__ void unpk(ull v, float& lo, float& hi) {
    unsigned a, b;
    asm("mov.b64 {%0, %1}, %2;" : "=r"(a), "=r"(b) : "l"(v));
    lo = __uint_as_float(a); hi = __uint_as_float(b);
}

// ---------------- device scratch ----------------
__device__ float g_GT[64*192];       // [c1*192 + h*64+c2]
__device__ float g_mwT[64*192];      // [c*192 + h*64+o]
__device__ float g_v1[NH*CC];
__device__ float g_v2[NH*CC];
__device__ float g_sc[NH];
__device__ float g_attm[NB*NH*FEAT];
__device__ float g_scale[NH*FEAT];
__device__ float g_shift[NH*FEAT];
__device__ float g_gcn[NB*CC*NN*LL];

// ---------------- k0: G^T, v1, v2, s  +  mw^T (blocks 3..50) ----------------
__global__ void k0_pre(const float* __restrict__ cw1, const float* __restrict__ cb1,
                       const float* __restrict__ cw2, const float* __restrict__ cb2,
                       const float* __restrict__ mw) {
    __shared__ float s1[4096];
    __shared__ float s2[4096];
    int blk = blockIdx.x, t = threadIdx.x;
    if (blk >= 3) {                       // mw^T part
        int i = (blk - 3) * 256 + t;
        if (i < 12288) {
            int c = i / 192, row = i % 192;
            g_mwT[i] = mw[row*64 + c];
        }
        return;
    }
    int h = blk;
    for (int i = t; i < 4096; i += 256) { s1[i] = cw1[h*4096+i]; s2[i] = cw2[h*4096+i]; }
    __syncthreads();
    for (int e = t; e < 4096; e += 256) {
        int c2 = e >> 6, c1 = e & 63;
        float acc = 0.f;
        #pragma unroll 8
        for (int o = 0; o < 64; o++) acc += s2[o*64+c2] * s1[o*64+c1];
        g_GT[c1*192 + h*64 + c2] = acc;
    }
    if (t < 64) {
        float a1 = 0.f, a2 = 0.f;
        for (int o = 0; o < 64; o++) {
            a1 += cb2[h*64+o] * s1[o*64+t];
            a2 += cb1[h*64+o] * s2[o*64+t];
        }
        g_v1[h*64+t] = a1;
        g_v2[h*64+t] = a2;
    }
    if (t == 64) {
        float a = 0.f;
        for (int o = 0; o < 64; o++) a += cb1[h*64+o]*cb2[h*64+o];
        g_sc[h] = a;
    }
}

// ---------------- k1: attention matrices, f32x2 over l-pairs (R9 exact) ----
// smem floats: sGT 12288 | sxt 64*48 | sW2 192*50 | sXs 1472 | st1 72 | st2 72
#define SM1_FLOATS (12288 + 3072 + 9600 + 1472 + 72 + 72)

__global__ __launch_bounds__(256, 2) void k1_attm(const float* __restrict__ x) {
    extern __shared__ float sm[];
    float* sGT = sm;            // [c1*192 + row]
    float* sxt = sGT + 12288;   // [c*48 + n*2 + li], n padded to 24, zeros
    float* sW2 = sxt + 3072;    // [(row*25 + n)*2 + li], 25-pair row stride
    float* sXs = sW2 + 9600;    // [c*23 + n]
    float* st1 = sXs + 1472;
    float* st2 = st1 + 72;

    int b = blockIdx.x, t = threadIdx.x;

    for (int i = t; i < 12288; i += 256) sGT[i] = g_GT[i];
    for (int i = t; i < 1472; i += 256) sXs[i] = 0.f;

    int rt = t & 63, ct = t >> 6;
    int r0 = rt * 3, n0 = ct * 6;

    int qh = t >> 6, s = t & 63;
    int m0 = (s & 7) * 3, nq0 = (s >> 3) * 3;
    bool qact = (t < 192);

    ull qp[3][3];
    #pragma unroll
    for (int i = 0; i < 3; i++)
        #pragma unroll
        for (int j = 0; j < 3; j++) qp[i][j] = 0ULL;

    const float* xb = x + b * (64*23*35);

    for (int p = 0; p < 18; p++) {
        int l0 = p * 2;
        __syncthreads();   // prev Q-phase reads done (and init on p=0)

        for (int idx = t; idx < 3072; idx += 256) {
            int c = idx / 48, r = idx - c*48;
            int n = r >> 1, li = r & 1;
            int l = l0 + li;
            sxt[idx] = (n < 23 && l < 35) ? xb[(c*23 + n)*35 + l] : 0.f;
        }
        __syncthreads();

        for (int e = t; e < 1472; e += 256) {
            int c = e / 23, n = e - c*23;
            sXs[e] += sxt[c*48 + n*2] + sxt[c*48 + n*2 + 1];
        }

        // ---- W phase
        {
            ull w2[3][6];
            #pragma unroll
            for (int i = 0; i < 3; i++)
                #pragma unroll
                for (int j = 0; j < 6; j++) w2[i][j] = 0ULL;
            #pragma unroll 4
            for (int c1 = 0; c1 < 64; c1++) {
                ull d0 = dup2(sGT[c1*192 + r0]);
                ull d1 = dup2(sGT[c1*192 + r0 + 1]);
                ull d2 = dup2(sGT[c1*192 + r0 + 2]);
                #pragma unroll
                for (int j = 0; j < 6; j++) {
                    ull xv = *reinterpret_cast<const ull*>(&sxt[c1*48 + (n0+j)*2]);
                    fma2(w2[0][j], d0, xv);
                    fma2(w2[1][j], d1, xv);
                    fma2(w2[2][j], d2, xv);
                }
            }
            #pragma unroll
            for (int i = 0; i < 3; i++)
                #pragma unroll
                for (int j = 0; j < 6; j++)
                    *reinterpret_cast<ull*>(&sW2[((r0+i)*25 + n0+j)*2]) = w2[i][j];
        }
        __syncthreads();

        // ---- Q phase
        if (qact) {
            int wb = qh * 64;
            #pragma unroll 2
            for (int c2 = 0; c2 < 64; c2++) {
                ull xm[3], wn[3];
                #pragma unroll
                for (int i = 0; i < 3; i++)
                    xm[i] = *reinterpret_cast<const ull*>(&sxt[c2*48 + (m0+i)*2]);
                #pragma unroll
                for (int j = 0; j < 3; j++)
                    wn[j] = *reinterpret_cast<const ull*>(&sW2[((wb+c2)*25 + nq0+j)*2]);
                #pragma unroll
                for (int i = 0; i < 3; i++)
                    #pragma unroll
                    for (int j = 0; j < 3; j++)
                        fma2(qp[i][j], xm[i], wn[j]);
            }
        }
    }
    __syncthreads();

    if (t < 69) {
        int h = t / 23, n = t % 23;
        float a = 0.f;
        #pragma unroll 8
        for (int c = 0; c < 64; c++) a += g_v1[h*64 + c] * sXs[c*23 + n];
        st1[t] = a;
    } else if (t < 138) {
        int tt = t - 69;
        int h = tt / 23, m = tt % 23;
        float a = 0.f;
        #pragma unroll 8
        for (int c = 0; c < 64; c++) a += g_v2[h*64 + c] * sXs[c*23 + m];
        st2[tt] = a;
    }
    __syncthreads();

    if (qact) {
        float base = 35.0f * g_sc[qh];
        #pragma unroll
        for (int i = 0; i < 3; i++) {
            int m = m0 + i; if (m >= 23) continue;
            #pragma unroll
            for (int j = 0; j < 3; j++) {
                int n = nq0 + j; if (n >= 23) continue;
                float lo, hi; unpk(qp[i][j], lo, hi);
                float val = (lo + hi + st2[qh*23 + m] + st1[qh*23 + n] + base) * KINV;
                g_attm[(b*NH + qh)*FEAT + m*23 + n] = val;
            }
        }
    }
}

// ---------------- k2: BN stats (R9 exact) ----------------
__global__ void k2_bn(const float* __restrict__ gamma, const float* __restrict__ beta) {
    __shared__ float ss[256];
    __shared__ float sq[256];
    int f = blockIdx.x, t = threadIdx.x;
    float v = g_attm[t*(NH*FEAT) + f];
    ss[t] = v; sq[t] = v*v;
    __syncthreads();
    for (int s = 128; s > 0; s >>= 1) {
        if (t < s) { ss[t] += ss[t+s]; sq[t] += sq[t+s]; }
        __syncthreads();
    }
    if (t == 0) {
        float mean = ss[0] * (1.0f/256.0f);
        float var  = sq[0] * (1.0f/256.0f) - mean*mean;
        float sc = gamma[f] * rsqrtf(var + 1e-5f);
        g_scale[f] = sc;
        g_shift[f] = beta[f] - mean * sc;
    }
}

// ---------------- k4: BN-apply + softmax prologue, then gcn (R9 core) -------
// smem floats: sA 1588 | sxt 9216 | sMX 9344 | smwT 4096
#define SM4_FLOATS (1588 + 9216 + 9344 + 4096)

__global__ __launch_bounds__(256, 2) void k4_gcn(const float* __restrict__ x,
                                                 const float* __restrict__ mb,
                                                 const float* __restrict__ att,
                                                 const float* __restrict__ A_ske) {
    extern __shared__ float sm[];
    float* sA   = sm;             // [h*529 + n*23 + m], padded to 1588
    float* sxt  = sA + 1588;      // [c*144 + n*6 + li], zero-pad  (8B-aligned)
    float* sMX  = sxt + 9216;     // [o*146 + n*6 + li]            (8B-aligned)
    float* smwT = sMX + 9344;     // [c*64 + o]

    int blk = blockIdx.x;
    int b = blk / 6, ch = blk % 6;
    int l0 = ch * 6;
    int t = threadIdx.x;

    // x fill (visible after first h-loop barrier pair)
    for (int idx = t; idx < 9216; idx += 256) {
        int c = idx / 144, r = idx - c*144;
        int n = r / 6, li = r - n*6;
        int l = l0 + li;
        sxt[idx] = (n < 23 && l < 35) ? x[((b*64 + c)*23 + n)*35 + l] : 0.f;
    }

    // ---- fused k3 prologue: sA = softmax_col(attm*scale+shift) + ske + att
    for (int i = t; i < 1587; i += 256)
        sA[i] = g_attm[b*1587 + i] * g_scale[i] + g_shift[i];
    __syncthreads();
    if (t < 69) {          // h = t/23, column n = t%23; softmax over m (stride 23)
        int h = t / 23, n = t - h*23;
        float* col = sA + h*FEAT + n;
        float mx = -1e30f;
        for (int m = 0; m < 23; m++) mx = fmaxf(mx, col[m*23]);
        float ssum = 0.f;
        for (int m = 0; m < 23; m++) {
            float e = expf(col[m*23] - mx);
            col[m*23] = e; ssum += e;
        }
        float inv = 1.0f / ssum;
        for (int m = 0; m < 23; m++) col[m*23] *= inv;
    }
    __syncthreads();
    for (int i = t; i < 1587; i += 256)
        sA[i] += A_ske[i] + att[i];

    int ro = t & 31, pg0 = (t >> 5) * 9;
    int go = t & 63, m0 = (t >> 6) * 6;
    ull gacc[6][3];
    #pragma unroll
    for (int j = 0; j < 6; j++)
        #pragma unroll
        for (int lp = 0; lp < 3; lp++) gacc[j][lp] = 0ULL;

    for (int h = 0; h < NH; h++) {
        __syncthreads();   // prev gcn done reading sMX; prologue sA/sxt done on h=0
        for (int i = t; i < 4096; i += 256)
            smwT[i] = g_mwT[(i >> 6)*192 + h*64 + (i & 63)];
        __syncthreads();   // smwT (+ sA/sxt on h=0) visible

        // MX[o][col] = sum_c mw[h,o,c] * X[c,col]
        {
            ull a0[9], a1[9];
            #pragma unroll
            for (int q = 0; q < 9; q++) { a0[q] = 0ULL; a1[q] = 0ULL; }
            #pragma unroll 4
            for (int c = 0; c < 64; c++) {
                ull w0 = dup2(smwT[c*64 + ro]);
                ull w1 = dup2(smwT[c*64 + ro + 32]);
                #pragma unroll
                for (int q = 0; q < 9; q++) {
                    ull xv = *reinterpret_cast<const ull*>(&sxt[c*144 + 2*(pg0+q)]);
                    fma2(a0[q], w0, xv);
                    fma2(a1[q], w1, xv);
                }
            }
            #pragma unroll
            for (int q = 0; q < 9; q++) {
                *reinterpret_cast<ull*>(&sMX[ro*146 + 2*(pg0+q)]) = a0[q];
                *reinterpret_cast<ull*>(&sMX[(ro+32)*146 + 2*(pg0+q)]) = a1[q];
            }
        }
        __syncthreads();   // sMX visible

        // gcn[o,m,li] += sum_n MX[o,n,li] * A[h,n,m]
        #pragma unroll 1
        for (int n = 0; n < 23; n++) {
            ull mx2[3];
            #pragma unroll
            for (int lp = 0; lp < 3; lp++)
                mx2[lp] = *reinterpret_cast<const ull*>(&sMX[go*146 + n*6 + 2*lp]);
            #pragma unroll
            for (int j = 0; j < 6; j++) {
                int m = m0 + j; if (m > 22) m = 22;
                ull av = dup2(sA[h*FEAT + n*23 + m]);
                #pragma unroll
                for (int lp = 0; lp < 3; lp++)
                    fma2(gacc[j][lp], av, mx2[lp]);
            }
        }
    }

    float mbs = mb[go] + mb[64 + go] + mb[128 + go];
    #pragma unroll
    for (int j = 0; j < 6; j++) {
        int m = m0 + j; if (m >= 23) continue;
        #pragma unroll
        for (int lp = 0; lp < 3; lp++) {
            float lo, hi; unpk(gacc[j][lp], lo, hi);
            int l = l0 + 2*lp;
            float* dst = &g_gcn[((b*64 + go)*23 + m)*35 + l];
            if (l < 35)     dst[0] = lo + mbs;
            if (l + 1 < 35) dst[1] = hi + mbs;
        }
    }
}

// ---------------- k5: out = gcn @ ws + bias, f32x2 (R9 exact) ----------------
__global__ __launch_bounds__(288) void k5_out(const float* __restrict__ ws,
                                              const float* __restrict__ bias,
                                              float* __restrict__ out) {
    __shared__ float sws2[35*36];
    __shared__ float sb[36];
    __shared__ float srow[64*35];
    int t = threadIdx.x;
    for (int i = t; i < 35*36; i += 288) {
        int l = i / 36, j = i - l*36;
        sws2[i] = (j < 35) ? ws[l*35 + j] : 0.f;
    }
    if (t < 36) sb[t] = (t < 35) ? bias[t] : 0.f;
    long long base = (long long)blockIdx.x * 2240;
    for (int i = t; i < 2240; i += 288) srow[i] = g_gcn[base + i];
    __syncthreads();

    int rg = t / 9, jg = t - rg*9;
    int r0 = rg*2;
    ull a00 = 0ULL, a01 = 0ULL, a10 = 0ULL, a11 = 0ULL;
    #pragma unroll 5
    for (int l = 0; l < 35; l++) {
        ull w0 = *reinterpret_cast<const ull*>(&sws2[l*36 + 4*jg]);
        ull w1 = *reinterpret_cast<const ull*>(&sws2[l*36 + 4*jg + 2]);
        ull s0 = dup2(srow[r0*35 + l]);
        ull s1 = dup2(srow[r0*35 + 35 + l]);
        fma2(a00, s0, w0); fma2(a01, s0, w1);
        fma2(a10, s1, w0); fma2(a11, s1, w1);
    }

    float v[2][4];
    unpk(a00, v[0][0], v[0][1]); unpk(a01, v[0][2], v[0][3]);
    unpk(a10, v[1][0], v[1][1]); unpk(a11, v[1][2], v[1][3]);
    #pragma unroll
    for (int rr = 0; rr < 2; rr++) {
        long long ob = base + (long long)(r0 + rr) * 35;
        #pragma unroll
        for (int q = 0; q < 4; q++) {
            int j = 4*jg + q;
            if (j < 35) out[ob + j] = v[rr][q] + sb[j];
        }
    }
}

// ---------------- host launch ----------------
extern "C" void kernel_launch(void* const* d_in, const int* in_sizes, int n_in,
                              void* d_out, int out_size) {
    const float* x      = (const float*)d_in[0];
    const float* cw1    = (const float*)d_in[1];
    const float* cb1    = (const float*)d_in[2];
    const float* cw2    = (const float*)d_in[3];
    const float* cb2    = (const float*)d_in[4];
    const float* gamma  = (const float*)d_in[5];
    const float* beta   = (const float*)d_in[6];
    const float* mw     = (const float*)d_in[7];
    const float* mb     = (const float*)d_in[8];
    const float* att    = (const float*)d_in[9];
    const float* A_ske  = (const float*)d_in[10];
    const float* ws     = (const float*)d_in[11];
    const float* bias   = (const float*)d_in[12];
    float* out = (float*)d_out;

    cudaFuncSetAttribute(k1_attm, cudaFuncAttributeMaxDynamicSharedMemorySize,
                         SM1_FLOATS * (int)sizeof(float));
    cudaFuncSetAttribute(k4_gcn, cudaFuncAttributeMaxDynamicSharedMemorySize,
                         SM4_FLOATS * (int)sizeof(float));

    k0_pre<<<51, 256>>>(cw1, cb1, cw2, cb2, mw);           // launch 1 (G + mwT)
    k1_attm<<<NB, 256, SM1_FLOATS * sizeof(float)>>>(x);   // launch 2
    k2_bn<<<NH*FEAT, 256>>>(gamma, beta);                  // launch 3
    k4_gcn<<<NB*6, 256, SM4_FLOATS * sizeof(float)>>>(x, mb, att, A_ske);  // launch 4 -> profiled
    k5_out<<<5888, 288>>>(ws, bias, out);                  // launch 5
}

// round 17
// speedup vs baseline: 1.0623x; 1.0134x over previous
#include <cuda_runtime.h>

#define NB 256
#define NH 3
#define CC 64
#define NN 23
#define LL 35
#define FEAT 529
#define KINV (1.0f/2240.0f)

typedef unsigned long long ull;

__device__ __forceinline__ void fma2(ull& d, ull a, ull b) {
    asm("fma.rn.f32x2 %0, %1, %2, %0;" : "+l"(d) : "l"(a), "l"(b));
}
__device__ __forceinline__ ull dup2(float v) {
    ull r; unsigned u = __float_as_uint(v);
    asm("mov.b64 %0, {%1, %1};" : "=l"(r) : "r"(u));
    return r;
}
__device__ __forceinline__ void unpk(ull v, float& lo, float& hi) {
    unsigned a, b;
    asm("mov.b64 {%0, %1}, %2;" : "=r"(a), "=r"(b) : "l"(v));
    lo = __uint_as_float(a); hi = __uint_as_float(b);
}

// ---------------- device scratch ----------------
__device__ float g_GT[64*192];       // [c1*192 + h*64+c2]
__device__ float g_mwT[64*192];      // [c*192 + h*64+o]
__device__ float g_v1[NH*CC];
__device__ float g_v2[NH*CC];
__device__ float g_sc[NH];
__device__ float g_attm[NB*NH*FEAT];
__device__ float g_scale[NH*FEAT];
__device__ float g_shift[NH*FEAT];
__device__ float g_A[NB*NH*FEAT];
__device__ float g_gcn[NB*CC*NN*LL];

// ---------------- k0: G^T, v1, v2, s  +  mw^T (blocks 3..50) ----------------
__global__ void k0_pre(const float* __restrict__ cw1, const float* __restrict__ cb1,
                       const float* __restrict__ cw2, const float* __restrict__ cb2,
                       const float* __restrict__ mw) {
    __shared__ float s1[4096];
    __shared__ float s2[4096];
    int blk = blockIdx.x, t = threadIdx.x;
    if (blk >= 3) {                       // mw^T part
        int i = (blk - 3) * 256 + t;
        if (i < 12288) {
            int c = i / 192, row = i % 192;
            g_mwT[i] = mw[row*64 + c];
        }
        return;
    }
    int h = blk;
    for (int i = t; i < 4096; i += 256) { s1[i] = cw1[h*4096+i]; s2[i] = cw2[h*4096+i]; }
    __syncthreads();
    for (int e = t; e < 4096; e += 256) {
        int c2 = e >> 6, c1 = e & 63;
        float acc = 0.f;
        #pragma unroll 8
        for (int o = 0; o < 64; o++) acc += s2[o*64+c2] * s1[o*64+c1];
        g_GT[c1*192 + h*64 + c2] = acc;
    }
    if (t < 64) {
        float a1 = 0.f, a2 = 0.f;
        for (int o = 0; o < 64; o++) {
            a1 += cb2[h*64+o] * s1[o*64+t];
            a2 += cb1[h*64+o] * s2[o*64+t];
        }
        g_v1[h*64+t] = a1;
        g_v2[h*64+t] = a2;
    }
    if (t == 64) {
        float a = 0.f;
        for (int o = 0; o < 64; o++) a += cb1[h*64+o]*cb2[h*64+o];
        g_sc[h] = a;
    }
}

// ---------------- k1: attention matrices, f32x2 over l-pairs (R9 exact) ----
#define SM1_FLOATS (12288 + 3072 + 9600 + 1472 + 72 + 72)

__global__ __launch_bounds__(256, 2) void k1_attm(const float* __restrict__ x) {
    extern __shared__ float sm[];
    float* sGT = sm;            // [c1*192 + row]
    float* sxt = sGT + 12288;   // [c*48 + n*2 + li], n padded to 24, zeros
    float* sW2 = sxt + 3072;    // [(row*25 + n)*2 + li], 25-pair row stride
    float* sXs = sW2 + 9600;    // [c*23 + n]
    float* st1 = sXs + 1472;
    float* st2 = st1 + 72;

    int b = blockIdx.x, t = threadIdx.x;

    for (int i = t; i < 12288; i += 256) sGT[i] = g_GT[i];
    for (int i = t; i < 1472; i += 256) sXs[i] = 0.f;

    int rt = t & 63, ct = t >> 6;
    int r0 = rt * 3, n0 = ct * 6;

    int qh = t >> 6, s = t & 63;
    int m0 = (s & 7) * 3, nq0 = (s >> 3) * 3;
    bool qact = (t < 192);

    ull qp[3][3];
    #pragma unroll
    for (int i = 0; i < 3; i++)
        #pragma unroll
        for (int j = 0; j < 3; j++) qp[i][j] = 0ULL;

    const float* xb = x + b * (64*23*35);

    for (int p = 0; p < 18; p++) {
        int l0 = p * 2;
        __syncthreads();

        for (int idx = t; idx < 3072; idx += 256) {
            int c = idx / 48, r = idx - c*48;
            int n = r >> 1, li = r & 1;
            int l = l0 + li;
            sxt[idx] = (n < 23 && l < 35) ? xb[(c*23 + n)*35 + l] : 0.f;
        }
        __syncthreads();

        for (int e = t; e < 1472; e += 256) {
            int c = e / 23, n = e - c*23;
            sXs[e] += sxt[c*48 + n*2] + sxt[c*48 + n*2 + 1];
        }

        {
            ull w2[3][6];
            #pragma unroll
            for (int i = 0; i < 3; i++)
                #pragma unroll
                for (int j = 0; j < 6; j++) w2[i][j] = 0ULL;
            #pragma unroll 4
            for (int c1 = 0; c1 < 64; c1++) {
                ull d0 = dup2(sGT[c1*192 + r0]);
                ull d1 = dup2(sGT[c1*192 + r0 + 1]);
                ull d2 = dup2(sGT[c1*192 + r0 + 2]);
                #pragma unroll
                for (int j = 0; j < 6; j++) {
                    ull xv = *reinterpret_cast<const ull*>(&sxt[c1*48 + (n0+j)*2]);
                    fma2(w2[0][j], d0, xv);
                    fma2(w2[1][j], d1, xv);
                    fma2(w2[2][j], d2, xv);
                }
            }
            #pragma unroll
            for (int i = 0; i < 3; i++)
                #pragma unroll
                for (int j = 0; j < 6; j++)
                    *reinterpret_cast<ull*>(&sW2[((r0+i)*25 + n0+j)*2]) = w2[i][j];
        }
        __syncthreads();

        if (qact) {
            int wb = qh * 64;
            #pragma unroll 2
            for (int c2 = 0; c2 < 64; c2++) {
                ull xm[3], wn[3];
                #pragma unroll
                for (int i = 0; i < 3; i++)
                    xm[i] = *reinterpret_cast<const ull*>(&sxt[c2*48 + (m0+i)*2]);
                #pragma unroll
                for (int j = 0; j < 3; j++)
                    wn[j] = *reinterpret_cast<const ull*>(&sW2[((wb+c2)*25 + nq0+j)*2]);
                #pragma unroll
                for (int i = 0; i < 3; i++)
                    #pragma unroll
                    for (int j = 0; j < 3; j++)
                        fma2(qp[i][j], xm[i], wn[j]);
            }
        }
    }
    __syncthreads();

    if (t < 69) {
        int h = t / 23, n = t % 23;
        float a = 0.f;
        #pragma unroll 8
        for (int c = 0; c < 64; c++) a += g_v1[h*64 + c] * sXs[c*23 + n];
        st1[t] = a;
    } else if (t < 138) {
        int tt = t - 69;
        int h = tt / 23, m = tt % 23;
        float a = 0.f;
        #pragma unroll 8
        for (int c = 0; c < 64; c++) a += g_v2[h*64 + c] * sXs[c*23 + m];
        st2[tt] = a;
    }
    __syncthreads();

    if (qact) {
        float base = 35.0f * g_sc[qh];
        #pragma unroll
        for (int i = 0; i < 3; i++) {
            int m = m0 + i; if (m >= 23) continue;
            #pragma unroll
            for (int j = 0; j < 3; j++) {
                int n = nq0 + j; if (n >= 23) continue;
                float lo, hi; unpk(qp[i][j], lo, hi);
                float val = (lo + hi + st2[qh*23 + m] + st1[qh*23 + n] + base) * KINV;
                g_attm[(b*NH + qh)*FEAT + m*23 + n] = val;
            }
        }
    }
}

// ---------------- k2: BN stats (R9 exact) ----------------
__global__ void k2_bn(const float* __restrict__ gamma, const float* __restrict__ beta) {
    __shared__ float ss[256];
    __shared__ float sq[256];
    int f = blockIdx.x, t = threadIdx.x;
    float v = g_attm[t*(NH*FEAT) + f];
    ss[t] = v; sq[t] = v*v;
    __syncthreads();
    for (int s = 128; s > 0; s >>= 1) {
        if (t < s) { ss[t] += ss[t+s]; sq[t] += sq[t+s]; }
        __syncthreads();
    }
    if (t == 0) {
        float mean = ss[0] * (1.0f/256.0f);
        float var  = sq[0] * (1.0f/256.0f) - mean*mean;
        float sc = gamma[f] * rsqrtf(var + 1e-5f);
        g_scale[f] = sc;
        g_shift[f] = beta[f] - mean * sc;
    }
}

// ---------------- k3: BN apply + softmax(-2) + A (R9 exact) ----------------
__global__ void k3_soft(const float* __restrict__ att, const float* __restrict__ A_ske) {
    __shared__ float sy[FEAT];
    int bh = blockIdx.x, h = bh % 3, t = threadIdx.x;
    for (int e = t; e < FEAT; e += 256)
        sy[e] = g_attm[bh*FEAT + e] * g_scale[h*FEAT + e] + g_shift[h*FEAT + e];
    __syncthreads();
    if (t < 23) {
        float mx = -1e30f;
        for (int m = 0; m < 23; m++) mx = fmaxf(mx, sy[m*23 + t]);
        float ssum = 0.f;
        for (int m = 0; m < 23; m++) {
            float e = expf(sy[m*23 + t] - mx);
            sy[m*23 + t] = e; ssum += e;
        }
        float inv = 1.0f / ssum;
        for (int m = 0; m < 23; m++) sy[m*23 + t] *= inv;
    }
    __syncthreads();
    for (int e = t; e < FEAT; e += 256)
        g_A[bh*FEAT + e] = A_ske[h*FEAT + e] + att[h*FEAT + e] + sy[e];
}

// ---------------- k4: graph convolution, f32x2, l-chunks of 4, OCC 3 --------
// smem floats: sA 1588 | sxt 64*96 | sMX 64*98 | smwT 4096 = 18,100 = 72,400 B
// occ3: 3*(72400+1024) = 220,272 <= 233,472 ; reg target 84/thread
#define SM4_FLOATS (1588 + 6144 + 6272 + 4096)
#define NCH4 9     // 9 chunks of 4 cover l=0..35 (pad)

__global__ __launch_bounds__(256, 3) void k4_gcn(const float* __restrict__ x,
                                                 const float* __restrict__ mb) {
    extern __shared__ float sm[];
    float* sA   = sm;             // [h*529 + n*23 + m], padded to 1588 (even)
    float* sxt  = sA + 1588;      // [c*96 + n*4 + li], n pad 24, zero-pad (8B-al)
    float* sMX  = sxt + 6144;     // [o*98 + n*4 + li]                    (8B-al)
    float* smwT = sMX + 6272;     // [c*64 + o]

    int blk = blockIdx.x;
    int b = blk / NCH4, ch = blk - b*NCH4;
    int l0 = ch * 4;
    int t = threadIdx.x;

    for (int i = t; i < 1587; i += 256) sA[i] = g_A[b*1587 + i];
    for (int idx = t; idx < 6144; idx += 256) {
        int c = idx / 96, r = idx - c*96;
        int n = r >> 2, li = r & 3;
        int l = l0 + li;
        sxt[idx] = (n < 23 && l < 35) ? x[((b*64 + c)*23 + n)*35 + l] : 0.f;
    }

    // MX mapping: rows {ro, ro+32}; 8 groups x 6 pairs = 48 pairs (96 cols)
    int ro = t & 31, pg0 = (t >> 5) * 6;

    // gcn mapping: o = t&63, m-tile of 6 at m0; 2 li-pairs
    int go = t & 63, m0 = (t >> 6) * 6;
    ull gacc[6][2];
    #pragma unroll
    for (int j = 0; j < 6; j++)
        #pragma unroll
        for (int lp = 0; lp < 2; lp++) gacc[j][lp] = 0ULL;

    for (int h = 0; h < NH; h++) {
        __syncthreads();   // prev gcn done reading sMX (and initial fills on h=0)
        for (int i = t; i < 4096; i += 256)
            smwT[i] = g_mwT[(i >> 6)*192 + h*64 + (i & 63)];
        __syncthreads();   // smwT (+ sA/sxt on h=0) visible

        // MX[o][col] = sum_c mw[h,o,c] * X[c,col]
        {
            ull a0[6], a1[6];
            #pragma unroll
            for (int q = 0; q < 6; q++) { a0[q] = 0ULL; a1[q] = 0ULL; }
            #pragma unroll 4
            for (int c = 0; c < 64; c++) {
                ull w0 = dup2(smwT[c*64 + ro]);
                ull w1 = dup2(smwT[c*64 + ro + 32]);
                #pragma unroll
                for (int q = 0; q < 6; q++) {
                    ull xv = *reinterpret_cast<const ull*>(&sxt[c*96 + 2*(pg0+q)]);
                    fma2(a0[q], w0, xv);
                    fma2(a1[q], w1, xv);
                }
            }
            #pragma unroll
            for (int q = 0; q < 6; q++) {
                *reinterpret_cast<ull*>(&sMX[ro*98 + 2*(pg0+q)]) = a0[q];
                *reinterpret_cast<ull*>(&sMX[(ro+32)*98 + 2*(pg0+q)]) = a1[q];
            }
        }
        __syncthreads();   // sMX visible

        // gcn[o,m,li] += sum_n MX[o,n,li] * A[h,n,m]
        #pragma unroll 1
        for (int n = 0; n < 23; n++) {
            ull mx2[2];
            #pragma unroll
            for (int lp = 0; lp < 2; lp++)
                mx2[lp] = *reinterpret_cast<const ull*>(&sMX[go*98 + n*4 + 2*lp]);
            #pragma unroll
            for (int j = 0; j < 6; j++) {
                int m = m0 + j; if (m > 22) m = 22;
                ull av = dup2(sA[h*FEAT + n*23 + m]);
                #pragma unroll
                for (int lp = 0; lp < 2; lp++)
                    fma2(gacc[j][lp], av, mx2[lp]);
            }
        }
    }

    float mbs = mb[go] + mb[64 + go] + mb[128 + go];
    #pragma unroll
    for (int j = 0; j < 6; j++) {
        int m = m0 + j; if (m >= 23) continue;
        #pragma unroll
        for (int lp = 0; lp < 2; lp++) {
            float lo, hi; unpk(gacc[j][lp], lo, hi);
            int l = l0 + 2*lp;
            float* dst = &g_gcn[((b*64 + go)*23 + m)*35 + l];
            if (l < 35)     dst[0] = lo + mbs;
            if (l + 1 < 35) dst[1] = hi + mbs;
        }
    }
}

// ---------------- k5: out = gcn @ ws + bias, f32x2 (R9 exact) ----------------
__global__ __launch_bounds__(288) void k5_out(const float* __restrict__ ws,
                                              const float* __restrict__ bias,
                                              float* __restrict__ out) {
    __shared__ float sws2[35*36];
    __shared__ float sb[36];
    __shared__ float srow[64*35];
    int t = threadIdx.x;
    for (int i = t; i < 35*36; i += 288) {
        int l = i / 36, j = i - l*36;
        sws2[i] = (j < 35) ? ws[l*35 + j] : 0.f;
    }
    if (t < 36) sb[t] = (t < 35) ? bias[t] : 0.f;
    long long base = (long long)blockIdx.x * 2240;
    for (int i = t; i < 2240; i += 288) srow[i] = g_gcn[base + i];
    __syncthreads();

    int rg = t / 9, jg = t - rg*9;
    int r0 = rg*2;
    ull a00 = 0ULL, a01 = 0ULL, a10 = 0ULL, a11 = 0ULL;
    #pragma unroll 5
    for (int l = 0; l < 35; l++) {
        ull w0 = *reinterpret_cast<const ull*>(&sws2[l*36 + 4*jg]);
        ull w1 = *reinterpret_cast<const ull*>(&sws2[l*36 + 4*jg + 2]);
        ull s0 = dup2(srow[r0*35 + l]);
        ull s1 = dup2(srow[r0*35 + 35 + l]);
        fma2(a00, s0, w0); fma2(a01, s0, w1);
        fma2(a10, s1, w0); fma2(a11, s1, w1);
    }

    float v[2][4];
    unpk(a00, v[0][0], v[0][1]); unpk(a01, v[0][2], v[0][3]);
    unpk(a10, v[1][0], v[1][1]); unpk(a11, v[1][2], v[1][3]);
    #pragma unroll
    for (int rr = 0; rr < 2; rr++) {
        long long ob = base + (long long)(r0 + rr) * 35;
        #pragma unroll
        for (int q = 0; q < 4; q++) {
            int j = 4*jg + q;
            if (j < 35) out[ob + j] = v[rr][q] + sb[j];
        }
    }
}

// ---------------- host launch ----------------
extern "C" void kernel_launch(void* const* d_in, const int* in_sizes, int n_in,
                              void* d_out, int out_size) {
    const float* x      = (const float*)d_in[0];
    const float* cw1    = (const float*)d_in[1];
    const float* cb1    = (const float*)d_in[2];
    const float* cw2    = (const float*)d_in[3];
    const float* cb2    = (const float*)d_in[4];
    const float* gamma  = (const float*)d_in[5];
    const float* beta   = (const float*)d_in[6];
    const float* mw     = (const float*)d_in[7];
    const float* mb     = (const float*)d_in[8];
    const float* att    = (const float*)d_in[9];
    const float* A_ske  = (const float*)d_in[10];
    const float* ws     = (const float*)d_in[11];
    const float* bias   = (const float*)d_in[12];
    float* out = (float*)d_out;

    cudaFuncSetAttribute(k1_attm, cudaFuncAttributeMaxDynamicSharedMemorySize,
                         SM1_FLOATS * (int)sizeof(float));
    cudaFuncSetAttribute(k4_gcn, cudaFuncAttributeMaxDynamicSharedMemorySize,
                         SM4_FLOATS * (int)sizeof(float));

    k0_pre<<<51, 256>>>(cw1, cb1, cw2, cb2, mw);
    k1_attm<<<NB, 256, SM1_FLOATS * sizeof(float)>>>(x);
    k2_bn<<<NH*FEAT, 256>>>(gamma, beta);
    k3_soft<<<NB*NH, 256>>>(att, A_ske);
    k4_gcn<<<NB*NCH4, 256, SM4_FLOATS * sizeof(float)>>>(x, mb);
    k5_out<<<5888, 288>>>(ws, bias, out);
}